// round 12
// baseline (speedup 1.0000x reference)
#include <cuda_runtime.h>
#include <cuda_fp16.h>
#include <cstdint>

#define BATCH 8
#define NSEQ  1024
#define DIM   512
#define NH    8
#define DH    64
#define BH    64
#define SCALE 0.044194173824159216f   // 512^-0.5
#define LOG2E 1.4426950408889634f

// ---------------- scratch (device globals: alloc-guard safe) ----------------
__device__ __half g_q1[BH*NSEQ*DH];
__device__ __half g_k1[BH*NSEQ*DH];
__device__ __half g_v1[BH*NSEQ*DH];
__device__ __half g_o1[BATCH*NSEQ*DIM];
__device__ __half g_q2[BH*NSEQ*DH];
__device__ __half g_k2[BH*NSEQ*DH];
__device__ __half g_v2[BH*NSEQ*DH];
__device__ __half g_att[BATCH*NSEQ*DIM];
__device__ __half g_xh[BATCH*NSEQ*DIM];
__device__ __half g_w1[DIM*3*DIM];     // fp16 W, original [K][N] layout
__device__ __half g_w2[DIM*3*DIM];
__device__ __half g_wn[DIM*DIM];

// ---------------- helpers ----------------
__device__ __forceinline__ uint32_t pkh2(float x, float y) {
    __half2 h = __floats2half2_rn(x, y);
    return *(uint32_t*)&h;
}
__device__ __forceinline__ float tanha(float x) {
    float r;
    asm("tanh.approx.f32 %0, %1;" : "=f"(r) : "f"(x));
    return r;
}
__device__ __forceinline__ void mma16(float* c, const uint32_t* a, const uint32_t* b) {
    asm volatile(
        "mma.sync.aligned.m16n8k16.row.col.f32.f16.f16.f32 "
        "{%0,%1,%2,%3}, {%4,%5,%6,%7}, {%8,%9}, {%0,%1,%2,%3};\n"
        : "+f"(c[0]), "+f"(c[1]), "+f"(c[2]), "+f"(c[3])
        : "r"(a[0]), "r"(a[1]), "r"(a[2]), "r"(a[3]), "r"(b[0]), "r"(b[1]));
}
__device__ __forceinline__ void ldsm4(uint32_t& r0, uint32_t& r1, uint32_t& r2, uint32_t& r3,
                                      uint32_t addr) {
    asm volatile("ldmatrix.sync.aligned.m8n8.x4.shared.b16 {%0,%1,%2,%3}, [%4];"
        : "=r"(r0), "=r"(r1), "=r"(r2), "=r"(r3) : "r"(addr));
}
__device__ __forceinline__ void ldsm4t(uint32_t& r0, uint32_t& r1, uint32_t& r2, uint32_t& r3,
                                       uint32_t addr) {
    asm volatile("ldmatrix.sync.aligned.m8n8.x4.trans.shared.b16 {%0,%1,%2,%3}, [%4];"
        : "=r"(r0), "=r"(r1), "=r"(r2), "=r"(r3) : "r"(addr));
}
__device__ __forceinline__ void cpa16(uint32_t dst, const void* src) {
    asm volatile("cp.async.cg.shared.global [%0], [%1], 16;" :: "r"(dst), "l"(src));
}
#define CP_COMMIT()  asm volatile("cp.async.commit_group;")
#define CP_WAIT(n)   asm volatile("cp.async.wait_group " #n ";")

// ---------------- fused pre-pass: f32 -> f16 for x + all 3 weights ----------
__global__ __launch_bounds__(256) void cvt_all(
    const float4* __restrict__ xs, uint4* __restrict__ xd, int n0,
    const float4* __restrict__ w1s, uint4* __restrict__ w1d, int n1,
    const float4* __restrict__ w2s, uint4* __restrict__ w2d, int n2,
    const float4* __restrict__ wns, uint4* __restrict__ wnd, int n3)
{
    int i = blockIdx.x * 256 + threadIdx.x;
    const float4* s; uint4* d;
    if (i < n0)             { s = xs;  d = xd;  }
    else if ((i -= n0) < n1){ s = w1s; d = w1d; }
    else if ((i -= n1) < n2){ s = w2s; d = w2d; }
    else if ((i -= n2) < n3){ s = wns; d = wnd; }
    else return;
    float4 a = s[2*i], b = s[2*i+1];
    uint4 o;
    o.x = pkh2(a.x, a.y); o.y = pkh2(a.z, a.w);
    o.z = pkh2(b.x, b.y); o.w = pkh2(b.z, b.w);
    d[i] = o;
}

// ---------------- GEMM: C[M,Nc] = A[M,512] @ W[512,Nc] + bias (fp16 mma) ----
// Block 128x128, 8 warps (warp 32x64), k-chunk 32, triple-buffered cp.async,
// single barrier per chunk. No minBlocks cap (regs ~100 are load-bearing).
template<int QKV>
__global__ __launch_bounds__(256) void gemm_h(
    const __half* __restrict__ A, const __half* __restrict__ W,
    const float* __restrict__ bias, float* __restrict__ C,
    __half* __restrict__ Qo, __half* __restrict__ Ko, __half* __restrict__ Vo,
    int Ncols, float qscale)
{
    extern __shared__ char smc[];
    const int tid = threadIdx.x, warp = tid >> 5, lane = tid & 31;
    const int wm = warp & 3, wn = warp >> 2, lr = lane >> 2, lc = lane & 3;
    const int row0 = blockIdx.y * 128, col0 = blockIdx.x * 128;
    const uint32_t smb = (uint32_t)__cvta_generic_to_shared(smc);

    float acc[2][8][4] = {};

    // prologue: chunks 0 and 1 -> bufs 0,1
    #pragma unroll
    for (int c = 0; c < 2; c++) {
        const int kt = c*32;
        #pragma unroll
        for (int p = 0; p < 2; p++) {
            const int s = tid + 256*p;
            const int ra = s >> 2, ca = s & 3;
            cpa16(smb + c*18944 + ra*80 + ca*16, A + (row0 + ra)*DIM + kt + ca*8);
            const int rb = s >> 4, cb = s & 15;
            cpa16(smb + c*18944 + 10240 + rb*272 + cb*16,
                  W + (kt + rb)*Ncols + col0 + cb*8);
        }
        CP_COMMIT();
    }

    for (int i = 0; i < 16; i++) {
        const int bu = i % 3;
        if (i < 15) { CP_WAIT(1); } else { CP_WAIT(0); }
        __syncthreads();   // chunk i ready; all warps done with chunk i-1

        if (i + 2 < 16) {
            const int nb = (i+2) % 3, kt = (i+2)*32;
            #pragma unroll
            for (int p = 0; p < 2; p++) {
                const int s = tid + 256*p;
                const int ra = s >> 2, ca = s & 3;
                cpa16(smb + nb*18944 + ra*80 + ca*16,
                      A + (row0 + ra)*DIM + kt + ca*8);
                const int rb = s >> 4, cb = s & 15;
                cpa16(smb + nb*18944 + 10240 + rb*272 + cb*16,
                      W + (kt + rb)*Ncols + col0 + cb*8);
            }
            CP_COMMIT();
        }

        const uint32_t bufb = smb + bu*18944;
        #pragma unroll
        for (int kg = 0; kg < 2; kg++) {
            uint32_t af[2][4];
            #pragma unroll
            for (int mt = 0; mt < 2; mt++)
                ldsm4(af[mt][0], af[mt][1], af[mt][2], af[mt][3],
                      bufb + (wm*32 + mt*16 + (lane & 15))*80 + (lane>>4)*16 + kg*32);
            #pragma unroll
            for (int nb2 = 0; nb2 < 4; nb2++) {
                uint32_t r0, r1, r2, r3;
                ldsm4t(r0, r1, r2, r3,
                       bufb + 10240
                       + (kg*16 + ((lane>>3)&1)*8 + (lane&7))*272
                       + wn*128 + nb2*32 + (lane>>4)*16);
                uint32_t bf0[2] = {r0, r1}, bf1[2] = {r2, r3};
                mma16(acc[0][2*nb2],   af[0], bf0);
                mma16(acc[0][2*nb2+1], af[0], bf1);
                mma16(acc[1][2*nb2],   af[1], bf0);
                mma16(acc[1][2*nb2+1], af[1], bf1);
            }
        }
    }

    // epilogue
    #pragma unroll
    for (int mt = 0; mt < 2; mt++) {
        const int rbase = row0 + wm*32 + mt*16 + lr;
        #pragma unroll
        for (int nt = 0; nt < 8; nt++) {
            const int cc = col0 + wn*64 + nt*8 + 2*lc;
            const float b0 = bias[cc], b1 = bias[cc+1];
            #pragma unroll
            for (int h2 = 0; h2 < 2; h2++) {
                const int r = rbase + h2*8;
                float v0 = acc[mt][nt][h2*2]   + b0;
                float v1 = acc[mt][nt][h2*2+1] + b1;
                if (QKV) {
                    const int part = cc >> 9;
                    const int hh   = (cc >> 6) & 7;
                    const int dd   = cc & 63;
                    const int bb   = r >> 10;
                    const int nn   = r & 1023;
                    const int bhh  = bb*NH + hh;
                    if (part == 0) { v0 *= qscale; v1 *= qscale; }
                    __half* dst = (part == 0) ? Qo : (part == 1) ? Ko : Vo;
                    *(uint32_t*)&dst[(bhh*NSEQ + nn)*DH + dd] = pkh2(v0, v1);
                } else {
                    *(float2*)&C[r*Ncols + cc] = make_float2(v0, v1);
                }
            }
        }
    }
}

// ---------------- flash attention (fp16 mma, triple-buffered) ----------------
// Block: 128 queries, 8 warps (16 rows each), 64-key tiles, single barrier/tile.
// STAGE1: sigmoid(z) = 0.5 + 0.5*tanh(z/2); the /2 is folded into Q (qscale=0.5).
//         One MUFU (tanh.approx) per element.
// STAGE2: scores arrive in the log2 domain (qscale = SCALE*log2e); p = exp2(s-m)
//         is a raw EX2. Deferred rescale triggers at +11.5 (= 8*log2e); lrow is
//         a per-thread partial, quad-reduced once at the end.
template<bool STAGE1>
__global__ __launch_bounds__(256) void attn_h(
    const __half* __restrict__ Q, const __half* __restrict__ K,
    const __half* __restrict__ V, const float* __restrict__ mask,
    __half* __restrict__ out)
{
    extern __shared__ char smc[];
    const int tid = threadIdx.x, warp = tid >> 5, lane = tid & 31;
    const int lr = lane >> 2, lc = lane & 3;
    const int bh = blockIdx.x, qt = blockIdx.y;
    const int b = bh >> 3, h = bh & 7;
    const uint32_t smb = (uint32_t)__cvta_generic_to_shared(smc);

    const __half* Qsrc = Q + (bh*NSEQ + qt*128)*DH;
    const __half* Ksrc = K + bh*NSEQ*DH;
    const __half* Vsrc = V + bh*NSEQ*DH;

    // ---- stage Q into buf 2 region, extract A-frags ----
    #pragma unroll
    for (int p = 0; p < 4; p++) {
        const int s = tid + 256*p;
        const int row = s >> 3, c8 = s & 7;
        cpa16(smb + 2*18432 + row*144 + c8*16, Qsrc + row*64 + c8*8);
    }
    CP_COMMIT();
    CP_WAIT(0);
    __syncthreads();

    uint32_t qf[4][4];
    #pragma unroll
    for (int kg = 0; kg < 4; kg++)
        ldsm4(qf[kg][0], qf[kg][1], qf[kg][2], qf[kg][3],
              smb + 2*18432 + (warp*16 + (lane & 15))*144 + (lane>>4)*16 + kg*32);
    __syncthreads();   // buf 2 free for tile 2

    // ---- prologue: tiles 0,1 -> bufs 0,1 ----
    #pragma unroll
    for (int c = 0; c < 2; c++) {
        #pragma unroll
        for (int p = 0; p < 2; p++) {
            const int s = tid + 256*p;
            const int row = s >> 3, c8 = s & 7;
            cpa16(smb + c*18432 + row*144 + c8*16,        Ksrc + (c*64 + row)*64 + c8*8);
            cpa16(smb + c*18432 + 9216 + row*144 + c8*16, Vsrc + (c*64 + row)*64 + c8*8);
        }
        CP_COMMIT();
    }

    float o[8][4] = {};
    float mrow[2] = {-1e30f, -1e30f}, lrow[2] = {0.f, 0.f};

    for (int t = 0; t < 16; t++) {
        const int bu = t % 3;
        if (t < 15) { CP_WAIT(1); } else { CP_WAIT(0); }
        __syncthreads();   // tile t ready; all warps done with tile t-1

        if (t + 2 < 16) {
            const int nb = (t+2) % 3;
            #pragma unroll
            for (int p = 0; p < 2; p++) {
                const int s = tid + 256*p;
                const int row = s >> 3, c8 = s & 7;
                cpa16(smb + nb*18432 + row*144 + c8*16,
                      Ksrc + ((t+2)*64 + row)*64 + c8*8);
                cpa16(smb + nb*18432 + 9216 + row*144 + c8*16,
                      Vsrc + ((t+2)*64 + row)*64 + c8*8);
            }
            CP_COMMIT();
        }

        const uint32_t kbuf = smb + bu*18432;

        // ---- S = Q @ K^T ----
        float s[8][4];
        #pragma unroll
        for (int nt = 0; nt < 8; nt++)
            #pragma unroll
            for (int u = 0; u < 4; u++) s[nt][u] = 0.f;
        #pragma unroll
        for (int kg = 0; kg < 4; kg++) {
            #pragma unroll
            for (int nt2 = 0; nt2 < 4; nt2++) {
                uint32_t r0, r1, r2, r3;
                ldsm4(r0, r1, r2, r3,
                      kbuf + (nt2*16 + ((lane>>4)&1)*8 + (lane&7))*144
                      + kg*32 + ((lane>>3)&1)*16);
                uint32_t bf0[2] = {r0, r1}, bf1[2] = {r2, r3};
                mma16(s[2*nt2],   qf[kg], bf0);
                mma16(s[2*nt2+1], qf[kg], bf1);
            }
        }

        // ---- elementwise ----
        if (STAGE1) {
            // s = 0.5*q·k (Q pre-scaled); sigmoid(z*m) = 0.5 + 0.5*tanh(s*m)
            const int qrow0 = qt*128 + warp*16 + lr;
            #pragma unroll
            for (int nt = 0; nt < 8; nt++) {
                const int ccol = t*64 + nt*8 + 2*lc;
                float2 m0v = *(const float2*)(mask + qrow0*NSEQ + ccol);
                float2 m1v = *(const float2*)(mask + (qrow0+8)*NSEQ + ccol);
                s[nt][0] = fmaf(0.5f, tanha(s[nt][0]*m0v.x), 0.5f);
                s[nt][1] = fmaf(0.5f, tanha(s[nt][1]*m0v.y), 0.5f);
                s[nt][2] = fmaf(0.5f, tanha(s[nt][2]*m1v.x), 0.5f);
                s[nt][3] = fmaf(0.5f, tanha(s[nt][3]*m1v.y), 0.5f);
            }
        } else {
            // per-row tile max (trigger only); log2 domain
            float tmax[2];
            #pragma unroll
            for (int h2 = 0; h2 < 2; h2++) {
                float tm = -1e30f;
                #pragma unroll
                for (int nt = 0; nt < 8; nt++)
                    tm = fmaxf(tm, fmaxf(s[nt][h2*2], s[nt][h2*2+1]));
                tm = fmaxf(tm, __shfl_xor_sync(0xffffffffu, tm, 1));
                tm = fmaxf(tm, __shfl_xor_sync(0xffffffffu, tm, 2));
                tmax[h2] = tm;
            }
            // deferred rescale: p <= 2^11.5 stays inside fp16 range
            const bool trig = (tmax[0] > mrow[0] + 11.5f) || (tmax[1] > mrow[1] + 11.5f);
            if (__any_sync(0xffffffffu, trig)) {
                #pragma unroll
                for (int h2 = 0; h2 < 2; h2++) {
                    const float mnew  = fmaxf(mrow[h2], tmax[h2]);
                    const float alpha = exp2f(mrow[h2] - mnew);
                    lrow[h2] *= alpha;
                    #pragma unroll
                    for (int nt = 0; nt < 8; nt++) {
                        o[nt][h2*2]   *= alpha;
                        o[nt][h2*2+1] *= alpha;
                    }
                    mrow[h2] = mnew;
                }
            }
            #pragma unroll
            for (int h2 = 0; h2 < 2; h2++) {
                float rs = 0.f;
                #pragma unroll
                for (int nt = 0; nt < 8; nt++) {
                    const float p0 = exp2f(s[nt][h2*2]   - mrow[h2]);
                    const float p1 = exp2f(s[nt][h2*2+1] - mrow[h2]);
                    rs += p0 + p1;
                    s[nt][h2*2]   = p0;
                    s[nt][h2*2+1] = p1;
                }
                lrow[h2] += rs;   // per-thread partial; quad-reduced at the end
            }
        }

        // ---- C-frag -> fp16 A-frag: pure register packing ----
        uint32_t pa[4][4];
        #pragma unroll
        for (int kt2 = 0; kt2 < 4; kt2++) {
            pa[kt2][0] = pkh2(s[2*kt2][0],   s[2*kt2][1]);
            pa[kt2][1] = pkh2(s[2*kt2][2],   s[2*kt2][3]);
            pa[kt2][2] = pkh2(s[2*kt2+1][0], s[2*kt2+1][1]);
            pa[kt2][3] = pkh2(s[2*kt2+1][2], s[2*kt2+1][3]);
        }

        // ---- O += P @ V : trans ldsm on row-major V ----
        const uint32_t vbuf = kbuf + 9216;
        #pragma unroll
        for (int kg = 0; kg < 4; kg++) {
            #pragma unroll
            for (int nb2 = 0; nb2 < 4; nb2++) {
                uint32_t r0, r1, r2, r3;
                ldsm4t(r0, r1, r2, r3,
                       vbuf + (kg*16 + ((lane>>3)&1)*8 + (lane&7))*144
                       + nb2*32 + (lane>>4)*16);
                uint32_t bf0[2] = {r0, r1}, bf1[2] = {r2, r3};
                mma16(o[2*nb2],   pa[kg], bf0);
                mma16(o[2*nb2+1], pa[kg], bf1);
            }
        }
    }

    // ---- final lrow reduction across the lane quad (stage 2 only) ----
    if (!STAGE1) {
        #pragma unroll
        for (int h2 = 0; h2 < 2; h2++) {
            float l = lrow[h2];
            l += __shfl_xor_sync(0xffffffffu, l, 1);
            l += __shfl_xor_sync(0xffffffffu, l, 2);
            lrow[h2] = l;
        }
    }

    // ---- epilogue: half output (feeds next GEMM) ----
    __half* obase = out + b*NSEQ*DIM + h*DH;
    #pragma unroll
    for (int h2 = 0; h2 < 2; h2++) {
        const float inv = STAGE1 ? 1.f : __fdividef(1.f, lrow[h2]);
        const int n = qt*128 + warp*16 + lr + h2*8;
        #pragma unroll
        for (int nt = 0; nt < 8; nt++)
            *(uint32_t*)&obase[n*DIM + nt*8 + 2*lc] =
                pkh2(o[nt][h2*2]*inv, o[nt][h2*2+1]*inv);
    }
}

// ---------------- launch ----------------
extern "C" void kernel_launch(void* const* d_in, const int* in_sizes, int n_in,
                              void* d_out, int out_size)
{
    const float* x     = (const float*)d_in[0];
    const float* mask  = (const float*)d_in[1];
    const float* Wqkv1 = (const float*)d_in[2];
    const float* bqkv1 = (const float*)d_in[3];
    const float* Wqkv2 = (const float*)d_in[4];
    const float* bqkv2 = (const float*)d_in[5];
    const float* Wnn1  = (const float*)d_in[6];
    const float* bnn1  = (const float*)d_in[7];
    float* out = (float*)d_out;

    __half *q1, *k1, *v1, *o1, *q2, *k2, *v2, *att, *xh, *w1, *w2, *wn;
    cudaGetSymbolAddress((void**)&q1, g_q1);
    cudaGetSymbolAddress((void**)&k1, g_k1);
    cudaGetSymbolAddress((void**)&v1, g_v1);
    cudaGetSymbolAddress((void**)&o1, g_o1);
    cudaGetSymbolAddress((void**)&q2, g_q2);
    cudaGetSymbolAddress((void**)&k2, g_k2);
    cudaGetSymbolAddress((void**)&v2, g_v2);
    cudaGetSymbolAddress((void**)&att, g_att);
    cudaGetSymbolAddress((void**)&xh, g_xh);
    cudaGetSymbolAddress((void**)&w1, g_w1);
    cudaGetSymbolAddress((void**)&w2, g_w2);
    cudaGetSymbolAddress((void**)&wn, g_wn);

    const int GSMEM = 56832, ASMEM = 55296;
    cudaFuncSetAttribute(gemm_h<1>, cudaFuncAttributeMaxDynamicSharedMemorySize, GSMEM);
    cudaFuncSetAttribute(gemm_h<0>, cudaFuncAttributeMaxDynamicSharedMemorySize, GSMEM);
    cudaFuncSetAttribute(attn_h<true>,  cudaFuncAttributeMaxDynamicSharedMemorySize, ASMEM);
    cudaFuncSetAttribute(attn_h<false>, cudaFuncAttributeMaxDynamicSharedMemorySize, ASMEM);

    const int M = BATCH * NSEQ;   // 8192
    const int n0 = M*DIM/8, n1 = DIM*3*DIM/8, n2 = n1, n3 = DIM*DIM/8;

    cvt_all<<<(n0+n1+n2+n3 + 255)/256, 256>>>(
        (const float4*)x, (uint4*)xh, n0,
        (const float4*)Wqkv1, (uint4*)w1, n1,
        (const float4*)Wqkv2, (uint4*)w2, n2,
        (const float4*)Wnn1, (uint4*)wn, n3);

    dim3 gridQKV(3*DIM/128, M/128);   // 12 x 64
    dim3 gridOut(DIM/128, M/128);     // 4 x 64
    dim3 gridAtt(BH, NSEQ/128);       // 64 x 8

    // Stage 1: Q scaled by 0.5 (tanh-sigmoid identity)
    gemm_h<1><<<gridQKV, 256, GSMEM>>>(xh, w1, bqkv1, nullptr, q1, k1, v1, 3*DIM, 0.5f);
    attn_h<true><<<gridAtt, 256, ASMEM>>>(q1, k1, v1, mask, o1);
    // Stage 2: Q scaled by SCALE*log2e (log2-domain softmax)
    gemm_h<1><<<gridQKV, 256, GSMEM>>>(o1, w2, bqkv2, nullptr, q2, k2, v2, 3*DIM, SCALE*LOG2E);
    attn_h<false><<<gridAtt, 256, ASMEM>>>(q2, k2, v2, nullptr, att);
    gemm_h<0><<<gridOut, 256, GSMEM>>>(att, wn, bnn1, out, nullptr, nullptr, nullptr, DIM, 1.f);
}

// round 13
// speedup vs baseline: 1.0055x; 1.0055x over previous
#include <cuda_runtime.h>
#include <cuda_fp16.h>
#include <cstdint>

#define BATCH 8
#define NSEQ  1024
#define DIM   512
#define NH    8
#define DH    64
#define BH    64
#define SCALE 0.044194173824159216f   // 512^-0.5
#define LOG2E 1.4426950408889634f

// ---------------- scratch (device globals: alloc-guard safe) ----------------
__device__ __half g_q1[BH*NSEQ*DH];
__device__ __half g_k1[BH*NSEQ*DH];
__device__ __half g_v1[BH*NSEQ*DH];
__device__ __half g_o1[BATCH*NSEQ*DIM];
__device__ __half g_q2[BH*NSEQ*DH];
__device__ __half g_k2[BH*NSEQ*DH];
__device__ __half g_v2[BH*NSEQ*DH];
__device__ __half g_att[BATCH*NSEQ*DIM];
__device__ __half g_xh[BATCH*NSEQ*DIM];
__device__ __half g_w1[DIM*3*DIM];     // fp16 W, original [K][N] layout
__device__ __half g_w2[DIM*3*DIM];
__device__ __half g_wn[DIM*DIM];

// ---------------- helpers ----------------
__device__ __forceinline__ uint32_t pkh2(float x, float y) {
    __half2 h = __floats2half2_rn(x, y);
    return *(uint32_t*)&h;
}
__device__ __forceinline__ float tanha(float x) {
    float r;
    asm("tanh.approx.f32 %0, %1;" : "=f"(r) : "f"(x));
    return r;
}
__device__ __forceinline__ float ex2a(float x) {   // raw EX2 (single MUFU)
    float r;
    asm("ex2.approx.f32 %0, %1;" : "=f"(r) : "f"(x));
    return r;
}
__device__ __forceinline__ void mma16(float* c, const uint32_t* a, const uint32_t* b) {
    asm volatile(
        "mma.sync.aligned.m16n8k16.row.col.f32.f16.f16.f32 "
        "{%0,%1,%2,%3}, {%4,%5,%6,%7}, {%8,%9}, {%0,%1,%2,%3};\n"
        : "+f"(c[0]), "+f"(c[1]), "+f"(c[2]), "+f"(c[3])
        : "r"(a[0]), "r"(a[1]), "r"(a[2]), "r"(a[3]), "r"(b[0]), "r"(b[1]));
}
__device__ __forceinline__ void ldsm4(uint32_t& r0, uint32_t& r1, uint32_t& r2, uint32_t& r3,
                                      uint32_t addr) {
    asm volatile("ldmatrix.sync.aligned.m8n8.x4.shared.b16 {%0,%1,%2,%3}, [%4];"
        : "=r"(r0), "=r"(r1), "=r"(r2), "=r"(r3) : "r"(addr));
}
__device__ __forceinline__ void ldsm4t(uint32_t& r0, uint32_t& r1, uint32_t& r2, uint32_t& r3,
                                       uint32_t addr) {
    asm volatile("ldmatrix.sync.aligned.m8n8.x4.trans.shared.b16 {%0,%1,%2,%3}, [%4];"
        : "=r"(r0), "=r"(r1), "=r"(r2), "=r"(r3) : "r"(addr));
}
__device__ __forceinline__ void cpa16(uint32_t dst, const void* src) {
    asm volatile("cp.async.cg.shared.global [%0], [%1], 16;" :: "r"(dst), "l"(src));
}
#define CP_COMMIT()  asm volatile("cp.async.commit_group;")
#define CP_WAIT(n)   asm volatile("cp.async.wait_group " #n ";")

// ---------------- fused pre-pass: f32 -> f16 for x + all 3 weights ----------
__global__ __launch_bounds__(256) void cvt_all(
    const float4* __restrict__ xs, uint4* __restrict__ xd, int n0,
    const float4* __restrict__ w1s, uint4* __restrict__ w1d, int n1,
    const float4* __restrict__ w2s, uint4* __restrict__ w2d, int n2,
    const float4* __restrict__ wns, uint4* __restrict__ wnd, int n3)
{
    int i = blockIdx.x * 256 + threadIdx.x;
    const float4* s; uint4* d;
    if (i < n0)             { s = xs;  d = xd;  }
    else if ((i -= n0) < n1){ s = w1s; d = w1d; }
    else if ((i -= n1) < n2){ s = w2s; d = w2d; }
    else if ((i -= n2) < n3){ s = wns; d = wnd; }
    else return;
    float4 a = s[2*i], b = s[2*i+1];
    uint4 o;
    o.x = pkh2(a.x, a.y); o.y = pkh2(a.z, a.w);
    o.z = pkh2(b.x, b.y); o.w = pkh2(b.z, b.w);
    d[i] = o;
}

// ---------------- GEMM: C[M,Nc] = A[M,512] @ W[512,Nc] + bias (fp16 mma) ----
// Block 128x128, 8 warps (warp 32x64), k-chunk 32, triple-buffered cp.async,
// single barrier per chunk. No minBlocks cap (regs ~100 are load-bearing).
template<int QKV>
__global__ __launch_bounds__(256) void gemm_h(
    const __half* __restrict__ A, const __half* __restrict__ W,
    const float* __restrict__ bias, float* __restrict__ C,
    __half* __restrict__ Qo, __half* __restrict__ Ko, __half* __restrict__ Vo,
    int Ncols, float qscale)
{
    extern __shared__ char smc[];
    const int tid = threadIdx.x, warp = tid >> 5, lane = tid & 31;
    const int wm = warp & 3, wn = warp >> 2, lr = lane >> 2, lc = lane & 3;
    const int row0 = blockIdx.y * 128, col0 = blockIdx.x * 128;
    const uint32_t smb = (uint32_t)__cvta_generic_to_shared(smc);

    float acc[2][8][4] = {};

    // prologue: chunks 0 and 1 -> bufs 0,1
    #pragma unroll
    for (int c = 0; c < 2; c++) {
        const int kt = c*32;
        #pragma unroll
        for (int p = 0; p < 2; p++) {
            const int s = tid + 256*p;
            const int ra = s >> 2, ca = s & 3;
            cpa16(smb + c*18944 + ra*80 + ca*16, A + (row0 + ra)*DIM + kt + ca*8);
            const int rb = s >> 4, cb = s & 15;
            cpa16(smb + c*18944 + 10240 + rb*272 + cb*16,
                  W + (kt + rb)*Ncols + col0 + cb*8);
        }
        CP_COMMIT();
    }

    for (int i = 0; i < 16; i++) {
        const int bu = i % 3;
        if (i < 15) { CP_WAIT(1); } else { CP_WAIT(0); }
        __syncthreads();   // chunk i ready; all warps done with chunk i-1

        if (i + 2 < 16) {
            const int nb = (i+2) % 3, kt = (i+2)*32;
            #pragma unroll
            for (int p = 0; p < 2; p++) {
                const int s = tid + 256*p;
                const int ra = s >> 2, ca = s & 3;
                cpa16(smb + nb*18944 + ra*80 + ca*16,
                      A + (row0 + ra)*DIM + kt + ca*8);
                const int rb = s >> 4, cb = s & 15;
                cpa16(smb + nb*18944 + 10240 + rb*272 + cb*16,
                      W + (kt + rb)*Ncols + col0 + cb*8);
            }
            CP_COMMIT();
        }

        const uint32_t bufb = smb + bu*18944;
        #pragma unroll
        for (int kg = 0; kg < 2; kg++) {
            uint32_t af[2][4];
            #pragma unroll
            for (int mt = 0; mt < 2; mt++)
                ldsm4(af[mt][0], af[mt][1], af[mt][2], af[mt][3],
                      bufb + (wm*32 + mt*16 + (lane & 15))*80 + (lane>>4)*16 + kg*32);
            #pragma unroll
            for (int nb2 = 0; nb2 < 4; nb2++) {
                uint32_t r0, r1, r2, r3;
                ldsm4t(r0, r1, r2, r3,
                       bufb + 10240
                       + (kg*16 + ((lane>>3)&1)*8 + (lane&7))*272
                       + wn*128 + nb2*32 + (lane>>4)*16);
                uint32_t bf0[2] = {r0, r1}, bf1[2] = {r2, r3};
                mma16(acc[0][2*nb2],   af[0], bf0);
                mma16(acc[0][2*nb2+1], af[0], bf1);
                mma16(acc[1][2*nb2],   af[1], bf0);
                mma16(acc[1][2*nb2+1], af[1], bf1);
            }
        }
    }

    // epilogue
    #pragma unroll
    for (int mt = 0; mt < 2; mt++) {
        const int rbase = row0 + wm*32 + mt*16 + lr;
        #pragma unroll
        for (int nt = 0; nt < 8; nt++) {
            const int cc = col0 + wn*64 + nt*8 + 2*lc;
            const float b0 = bias[cc], b1 = bias[cc+1];
            #pragma unroll
            for (int h2 = 0; h2 < 2; h2++) {
                const int r = rbase + h2*8;
                float v0 = acc[mt][nt][h2*2]   + b0;
                float v1 = acc[mt][nt][h2*2+1] + b1;
                if (QKV) {
                    const int part = cc >> 9;
                    const int hh   = (cc >> 6) & 7;
                    const int dd   = cc & 63;
                    const int bb   = r >> 10;
                    const int nn   = r & 1023;
                    const int bhh  = bb*NH + hh;
                    if (part == 0) { v0 *= qscale; v1 *= qscale; }
                    __half* dst = (part == 0) ? Qo : (part == 1) ? Ko : Vo;
                    *(uint32_t*)&dst[(bhh*NSEQ + nn)*DH + dd] = pkh2(v0, v1);
                } else {
                    *(float2*)&C[r*Ncols + cc] = make_float2(v0, v1);
                }
            }
        }
    }
}

// ---------------- flash attention (fp16 mma, triple-buffered) ----------------
// Block: 128 queries, 8 warps (16 rows each), 64-key tiles, single barrier/tile.
// STAGE1: sigmoid(z) = 0.5 + 0.5*tanh(z/2), /2 folded into Q. One MUFU/element.
// STAGE2: log2-domain scores (qscale = SCALE*log2e); p = ex2.approx(s - m) is a
//         single raw MUFU. Deferred rescale at +11.5; lrow per-thread partial,
//         quad-reduced once at the end.
template<bool STAGE1>
__global__ __launch_bounds__(256) void attn_h(
    const __half* __restrict__ Q, const __half* __restrict__ K,
    const __half* __restrict__ V, const float* __restrict__ mask,
    __half* __restrict__ out)
{
    extern __shared__ char smc[];
    const int tid = threadIdx.x, warp = tid >> 5, lane = tid & 31;
    const int lr = lane >> 2, lc = lane & 3;
    const int bh = blockIdx.x, qt = blockIdx.y;
    const int b = bh >> 3, h = bh & 7;
    const uint32_t smb = (uint32_t)__cvta_generic_to_shared(smc);

    const __half* Qsrc = Q + (bh*NSEQ + qt*128)*DH;
    const __half* Ksrc = K + bh*NSEQ*DH;
    const __half* Vsrc = V + bh*NSEQ*DH;

    // ---- stage Q into buf 2 region, extract A-frags ----
    #pragma unroll
    for (int p = 0; p < 4; p++) {
        const int s = tid + 256*p;
        const int row = s >> 3, c8 = s & 7;
        cpa16(smb + 2*18432 + row*144 + c8*16, Qsrc + row*64 + c8*8);
    }
    CP_COMMIT();
    CP_WAIT(0);
    __syncthreads();

    uint32_t qf[4][4];
    #pragma unroll
    for (int kg = 0; kg < 4; kg++)
        ldsm4(qf[kg][0], qf[kg][1], qf[kg][2], qf[kg][3],
              smb + 2*18432 + (warp*16 + (lane & 15))*144 + (lane>>4)*16 + kg*32);
    __syncthreads();   // buf 2 free for tile 2

    // ---- prologue: tiles 0,1 -> bufs 0,1 ----
    #pragma unroll
    for (int c = 0; c < 2; c++) {
        #pragma unroll
        for (int p = 0; p < 2; p++) {
            const int s = tid + 256*p;
            const int row = s >> 3, c8 = s & 7;
            cpa16(smb + c*18432 + row*144 + c8*16,        Ksrc + (c*64 + row)*64 + c8*8);
            cpa16(smb + c*18432 + 9216 + row*144 + c8*16, Vsrc + (c*64 + row)*64 + c8*8);
        }
        CP_COMMIT();
    }

    float o[8][4] = {};
    float mrow[2] = {-1e30f, -1e30f}, lrow[2] = {0.f, 0.f};

    for (int t = 0; t < 16; t++) {
        const int bu = t % 3;
        if (t < 15) { CP_WAIT(1); } else { CP_WAIT(0); }
        __syncthreads();   // tile t ready; all warps done with tile t-1

        if (t + 2 < 16) {
            const int nb = (t+2) % 3;
            #pragma unroll
            for (int p = 0; p < 2; p++) {
                const int s = tid + 256*p;
                const int row = s >> 3, c8 = s & 7;
                cpa16(smb + nb*18432 + row*144 + c8*16,
                      Ksrc + ((t+2)*64 + row)*64 + c8*8);
                cpa16(smb + nb*18432 + 9216 + row*144 + c8*16,
                      Vsrc + ((t+2)*64 + row)*64 + c8*8);
            }
            CP_COMMIT();
        }

        const uint32_t kbuf = smb + bu*18432;

        // ---- S = Q @ K^T ----
        float s[8][4];
        #pragma unroll
        for (int nt = 0; nt < 8; nt++)
            #pragma unroll
            for (int u = 0; u < 4; u++) s[nt][u] = 0.f;
        #pragma unroll
        for (int kg = 0; kg < 4; kg++) {
            #pragma unroll
            for (int nt2 = 0; nt2 < 4; nt2++) {
                uint32_t r0, r1, r2, r3;
                ldsm4(r0, r1, r2, r3,
                      kbuf + (nt2*16 + ((lane>>4)&1)*8 + (lane&7))*144
                      + kg*32 + ((lane>>3)&1)*16);
                uint32_t bf0[2] = {r0, r1}, bf1[2] = {r2, r3};
                mma16(s[2*nt2],   qf[kg], bf0);
                mma16(s[2*nt2+1], qf[kg], bf1);
            }
        }

        // ---- elementwise ----
        if (STAGE1) {
            const int qrow0 = qt*128 + warp*16 + lr;
            #pragma unroll
            for (int nt = 0; nt < 8; nt++) {
                const int ccol = t*64 + nt*8 + 2*lc;
                float2 m0v = *(const float2*)(mask + qrow0*NSEQ + ccol);
                float2 m1v = *(const float2*)(mask + (qrow0+8)*NSEQ + ccol);
                s[nt][0] = fmaf(0.5f, tanha(s[nt][0]*m0v.x), 0.5f);
                s[nt][1] = fmaf(0.5f, tanha(s[nt][1]*m0v.y), 0.5f);
                s[nt][2] = fmaf(0.5f, tanha(s[nt][2]*m1v.x), 0.5f);
                s[nt][3] = fmaf(0.5f, tanha(s[nt][3]*m1v.y), 0.5f);
            }
        } else {
            // per-row tile max (trigger only); log2 domain
            float tmax[2];
            #pragma unroll
            for (int h2 = 0; h2 < 2; h2++) {
                float tm = -1e30f;
                #pragma unroll
                for (int nt = 0; nt < 8; nt++)
                    tm = fmaxf(tm, fmaxf(s[nt][h2*2], s[nt][h2*2+1]));
                tm = fmaxf(tm, __shfl_xor_sync(0xffffffffu, tm, 1));
                tm = fmaxf(tm, __shfl_xor_sync(0xffffffffu, tm, 2));
                tmax[h2] = tm;
            }
            // deferred rescale: p <= 2^11.5 stays inside fp16 range
            const bool trig = (tmax[0] > mrow[0] + 11.5f) || (tmax[1] > mrow[1] + 11.5f);
            if (__any_sync(0xffffffffu, trig)) {
                #pragma unroll
                for (int h2 = 0; h2 < 2; h2++) {
                    const float mnew  = fmaxf(mrow[h2], tmax[h2]);
                    const float alpha = ex2a(mrow[h2] - mnew);
                    lrow[h2] *= alpha;
                    #pragma unroll
                    for (int nt = 0; nt < 8; nt++) {
                        o[nt][h2*2]   *= alpha;
                        o[nt][h2*2+1] *= alpha;
                    }
                    mrow[h2] = mnew;
                }
            }
            #pragma unroll
            for (int h2 = 0; h2 < 2; h2++) {
                float rs = 0.f;
                #pragma unroll
                for (int nt = 0; nt < 8; nt++) {
                    const float p0 = ex2a(s[nt][h2*2]   - mrow[h2]);
                    const float p1 = ex2a(s[nt][h2*2+1] - mrow[h2]);
                    rs += p0 + p1;
                    s[nt][h2*2]   = p0;
                    s[nt][h2*2+1] = p1;
                }
                lrow[h2] += rs;   // per-thread partial; quad-reduced at the end
            }
        }

        // ---- C-frag -> fp16 A-frag: pure register packing ----
        uint32_t pa[4][4];
        #pragma unroll
        for (int kt2 = 0; kt2 < 4; kt2++) {
            pa[kt2][0] = pkh2(s[2*kt2][0],   s[2*kt2][1]);
            pa[kt2][1] = pkh2(s[2*kt2][2],   s[2*kt2][3]);
            pa[kt2][2] = pkh2(s[2*kt2+1][0], s[2*kt2+1][1]);
            pa[kt2][3] = pkh2(s[2*kt2+1][2], s[2*kt2+1][3]);
        }

        // ---- O += P @ V : trans ldsm on row-major V ----
        const uint32_t vbuf = kbuf + 9216;
        #pragma unroll
        for (int kg = 0; kg < 4; kg++) {
            #pragma unroll
            for (int nb2 = 0; nb2 < 4; nb2++) {
                uint32_t r0, r1, r2, r3;
                ldsm4t(r0, r1, r2, r3,
                       vbuf + (kg*16 + ((lane>>3)&1)*8 + (lane&7))*144
                       + nb2*32 + (lane>>4)*16);
                uint32_t bf0[2] = {r0, r1}, bf1[2] = {r2, r3};
                mma16(o[2*nb2],   pa[kg], bf0);
                mma16(o[2*nb2+1], pa[kg], bf1);
            }
        }
    }

    // ---- final lrow reduction across the lane quad (stage 2 only) ----
    if (!STAGE1) {
        #pragma unroll
        for (int h2 = 0; h2 < 2; h2++) {
            float l = lrow[h2];
            l += __shfl_xor_sync(0xffffffffu, l, 1);
            l += __shfl_xor_sync(0xffffffffu, l, 2);
            lrow[h2] = l;
        }
    }

    // ---- epilogue: half output (feeds next GEMM) ----
    __half* obase = out + b*NSEQ*DIM + h*DH;
    #pragma unroll
    for (int h2 = 0; h2 < 2; h2++) {
        const float inv = STAGE1 ? 1.f : __fdividef(1.f, lrow[h2]);
        const int n = qt*128 + warp*16 + lr + h2*8;
        #pragma unroll
        for (int nt = 0; nt < 8; nt++)
            *(uint32_t*)&obase[n*DIM + nt*8 + 2*lc] =
                pkh2(o[nt][h2*2]*inv, o[nt][h2*2+1]*inv);
    }
}

// ---------------- launch ----------------
extern "C" void kernel_launch(void* const* d_in, const int* in_sizes, int n_in,
                              void* d_out, int out_size)
{
    const float* x     = (const float*)d_in[0];
    const float* mask  = (const float*)d_in[1];
    const float* Wqkv1 = (const float*)d_in[2];
    const float* bqkv1 = (const float*)d_in[3];
    const float* Wqkv2 = (const float*)d_in[4];
    const float* bqkv2 = (const float*)d_in[5];
    const float* Wnn1  = (const float*)d_in[6];
    const float* bnn1  = (const float*)d_in[7];
    float* out = (float*)d_out;

    __half *q1, *k1, *v1, *o1, *q2, *k2, *v2, *att, *xh, *w1, *w2, *wn;
    cudaGetSymbolAddress((void**)&q1, g_q1);
    cudaGetSymbolAddress((void**)&k1, g_k1);
    cudaGetSymbolAddress((void**)&v1, g_v1);
    cudaGetSymbolAddress((void**)&o1, g_o1);
    cudaGetSymbolAddress((void**)&q2, g_q2);
    cudaGetSymbolAddress((void**)&k2, g_k2);
    cudaGetSymbolAddress((void**)&v2, g_v2);
    cudaGetSymbolAddress((void**)&att, g_att);
    cudaGetSymbolAddress((void**)&xh, g_xh);
    cudaGetSymbolAddress((void**)&w1, g_w1);
    cudaGetSymbolAddress((void**)&w2, g_w2);
    cudaGetSymbolAddress((void**)&wn, g_wn);

    const int GSMEM = 56832, ASMEM = 55296;
    cudaFuncSetAttribute(gemm_h<1>, cudaFuncAttributeMaxDynamicSharedMemorySize, GSMEM);
    cudaFuncSetAttribute(gemm_h<0>, cudaFuncAttributeMaxDynamicSharedMemorySize, GSMEM);
    cudaFuncSetAttribute(attn_h<true>,  cudaFuncAttributeMaxDynamicSharedMemorySize, ASMEM);
    cudaFuncSetAttribute(attn_h<false>, cudaFuncAttributeMaxDynamicSharedMemorySize, ASMEM);

    const int M = BATCH * NSEQ;   // 8192
    const int n0 = M*DIM/8, n1 = DIM*3*DIM/8, n2 = n1, n3 = DIM*DIM/8;

    cvt_all<<<(n0+n1+n2+n3 + 255)/256, 256>>>(
        (const float4*)x, (uint4*)xh, n0,
        (const float4*)Wqkv1, (uint4*)w1, n1,
        (const float4*)Wqkv2, (uint4*)w2, n2,
        (const float4*)Wnn1, (uint4*)wn, n3);

    dim3 gridQKV(3*DIM/128, M/128);   // 12 x 64
    dim3 gridOut(DIM/128, M/128);     // 4 x 64
    dim3 gridAtt(BH, NSEQ/128);       // 64 x 8

    // Stage 1: Q scaled by 0.5 (tanh-sigmoid identity)
    gemm_h<1><<<gridQKV, 256, GSMEM>>>(xh, w1, bqkv1, nullptr, q1, k1, v1, 3*DIM, 0.5f);
    attn_h<true><<<gridAtt, 256, ASMEM>>>(q1, k1, v1, mask, o1);
    // Stage 2: Q scaled by SCALE*log2e (log2-domain softmax)
    gemm_h<1><<<gridQKV, 256, GSMEM>>>(o1, w2, bqkv2, nullptr, q2, k2, v2, 3*DIM, SCALE*LOG2E);
    attn_h<false><<<gridAtt, 256, ASMEM>>>(q2, k2, v2, nullptr, att);
    gemm_h<0><<<gridOut, 256, GSMEM>>>(att, wn, bnn1, out, nullptr, nullptr, nullptr, DIM, 1.f);
}

// round 14
// speedup vs baseline: 1.1148x; 1.1088x over previous
#include <cuda_runtime.h>
#include <cuda_fp16.h>
#include <cstdint>

#define BATCH 8
#define NSEQ  1024
#define DIM   512
#define NH    8
#define DH    64
#define BH    64
#define SCALE 0.044194173824159216f   // 512^-0.5
#define LOG2E 1.4426950408889634f

// ---------------- scratch (device globals: alloc-guard safe) ----------------
__device__ __half g_q1[BH*NSEQ*DH];
__device__ __half g_k1[BH*NSEQ*DH];
__device__ __half g_v1[BH*NSEQ*DH];
__device__ __half g_o1[BATCH*NSEQ*DIM];
__device__ __half g_q2[BH*NSEQ*DH];
__device__ __half g_k2[BH*NSEQ*DH];
__device__ __half g_v2[BH*NSEQ*DH];
__device__ __half g_att[BATCH*NSEQ*DIM];
__device__ __half g_xh[BATCH*NSEQ*DIM];
__device__ __half g_w1[DIM*3*DIM];     // fp16 W, original [K][N] layout
__device__ __half g_w2[DIM*3*DIM];
__device__ __half g_wn[DIM*DIM];
__device__ float  g_mask2[NSEQ*NSEQ];  // mask * (-log2e), fp32

// ---------------- helpers ----------------
__device__ __forceinline__ uint32_t pkh2(float x, float y) {
    __half2 h = __floats2half2_rn(x, y);
    return *(uint32_t*)&h;
}
__device__ __forceinline__ float ex2a(float x) {   // raw EX2 (single MUFU)
    float r;
    asm("ex2.approx.f32 %0, %1;" : "=f"(r) : "f"(x));
    return r;
}
__device__ __forceinline__ void mma16(float* c, const uint32_t* a, const uint32_t* b) {
    asm volatile(
        "mma.sync.aligned.m16n8k16.row.col.f32.f16.f16.f32 "
        "{%0,%1,%2,%3}, {%4,%5,%6,%7}, {%8,%9}, {%0,%1,%2,%3};\n"
        : "+f"(c[0]), "+f"(c[1]), "+f"(c[2]), "+f"(c[3])
        : "r"(a[0]), "r"(a[1]), "r"(a[2]), "r"(a[3]), "r"(b[0]), "r"(b[1]));
}
__device__ __forceinline__ void ldsm4(uint32_t& r0, uint32_t& r1, uint32_t& r2, uint32_t& r3,
                                      uint32_t addr) {
    asm volatile("ldmatrix.sync.aligned.m8n8.x4.shared.b16 {%0,%1,%2,%3}, [%4];"
        : "=r"(r0), "=r"(r1), "=r"(r2), "=r"(r3) : "r"(addr));
}
__device__ __forceinline__ void ldsm4t(uint32_t& r0, uint32_t& r1, uint32_t& r2, uint32_t& r3,
                                       uint32_t addr) {
    asm volatile("ldmatrix.sync.aligned.m8n8.x4.trans.shared.b16 {%0,%1,%2,%3}, [%4];"
        : "=r"(r0), "=r"(r1), "=r"(r2), "=r"(r3) : "r"(addr));
}
__device__ __forceinline__ void cpa16(uint32_t dst, const void* src) {
    asm volatile("cp.async.cg.shared.global [%0], [%1], 16;" :: "r"(dst), "l"(src));
}
#define CP_COMMIT()  asm volatile("cp.async.commit_group;")
#define CP_WAIT(n)   asm volatile("cp.async.wait_group " #n ";")

// ---------------- fused pre-pass: f32 -> f16 for x + weights; mask scale -----
__global__ __launch_bounds__(256) void cvt_all(
    const float4* __restrict__ xs, uint4* __restrict__ xd, int n0,
    const float4* __restrict__ w1s, uint4* __restrict__ w1d, int n1,
    const float4* __restrict__ w2s, uint4* __restrict__ w2d, int n2,
    const float4* __restrict__ wns, uint4* __restrict__ wnd, int n3,
    const float4* __restrict__ ms, float4* __restrict__ md, int n4)
{
    int i = blockIdx.x * 256 + threadIdx.x;
    if (i < n0 + n1 + n2 + n3) {
        const float4* s; uint4* d;
        if (i < n0)             { s = xs;  d = xd;  }
        else if ((i -= n0) < n1){ s = w1s; d = w1d; }
        else if ((i -= n1) < n2){ s = w2s; d = w2d; }
        else                    { i -= n2; s = wns; d = wnd; }
        float4 a = s[2*i], b = s[2*i+1];
        uint4 o;
        o.x = pkh2(a.x, a.y); o.y = pkh2(a.z, a.w);
        o.z = pkh2(b.x, b.y); o.w = pkh2(b.z, b.w);
        d[i] = o;
    } else {
        int j = i - (n0 + n1 + n2 + n3);
        if (j < n4) {
            float4 m = ms[j];
            md[j] = make_float4(m.x * -LOG2E, m.y * -LOG2E,
                                m.z * -LOG2E, m.w * -LOG2E);
        }
    }
}

// ---------------- GEMM: C[M,Nc] = A[M,512] @ W[512,Nc] + bias (fp16 mma) ----
// Block 128x128, 8 warps (warp 32x64), k-chunk 32, triple-buffered cp.async,
// single barrier per chunk. No minBlocks cap (regs ~100 are load-bearing).
template<int QKV>
__global__ __launch_bounds__(256) void gemm_h(
    const __half* __restrict__ A, const __half* __restrict__ W,
    const float* __restrict__ bias, float* __restrict__ C,
    __half* __restrict__ Qo, __half* __restrict__ Ko, __half* __restrict__ Vo,
    int Ncols, float qscale)
{
    extern __shared__ char smc[];
    const int tid = threadIdx.x, warp = tid >> 5, lane = tid & 31;
    const int wm = warp & 3, wn = warp >> 2, lr = lane >> 2, lc = lane & 3;
    const int row0 = blockIdx.y * 128, col0 = blockIdx.x * 128;
    const uint32_t smb = (uint32_t)__cvta_generic_to_shared(smc);

    float acc[2][8][4] = {};

    // prologue: chunks 0 and 1 -> bufs 0,1
    #pragma unroll
    for (int c = 0; c < 2; c++) {
        const int kt = c*32;
        #pragma unroll
        for (int p = 0; p < 2; p++) {
            const int s = tid + 256*p;
            const int ra = s >> 2, ca = s & 3;
            cpa16(smb + c*18944 + ra*80 + ca*16, A + (row0 + ra)*DIM + kt + ca*8);
            const int rb = s >> 4, cb = s & 15;
            cpa16(smb + c*18944 + 10240 + rb*272 + cb*16,
                  W + (kt + rb)*Ncols + col0 + cb*8);
        }
        CP_COMMIT();
    }

    for (int i = 0; i < 16; i++) {
        const int bu = i % 3;
        if (i < 15) { CP_WAIT(1); } else { CP_WAIT(0); }
        __syncthreads();   // chunk i ready; all warps done with chunk i-1

        if (i + 2 < 16) {
            const int nb = (i+2) % 3, kt = (i+2)*32;
            #pragma unroll
            for (int p = 0; p < 2; p++) {
                const int s = tid + 256*p;
                const int ra = s >> 2, ca = s & 3;
                cpa16(smb + nb*18944 + ra*80 + ca*16,
                      A + (row0 + ra)*DIM + kt + ca*8);
                const int rb = s >> 4, cb = s & 15;
                cpa16(smb + nb*18944 + 10240 + rb*272 + cb*16,
                      W + (kt + rb)*Ncols + col0 + cb*8);
            }
            CP_COMMIT();
        }

        const uint32_t bufb = smb + bu*18944;
        #pragma unroll
        for (int kg = 0; kg < 2; kg++) {
            uint32_t af[2][4];
            #pragma unroll
            for (int mt = 0; mt < 2; mt++)
                ldsm4(af[mt][0], af[mt][1], af[mt][2], af[mt][3],
                      bufb + (wm*32 + mt*16 + (lane & 15))*80 + (lane>>4)*16 + kg*32);
            #pragma unroll
            for (int nb2 = 0; nb2 < 4; nb2++) {
                uint32_t r0, r1, r2, r3;
                ldsm4t(r0, r1, r2, r3,
                       bufb + 10240
                       + (kg*16 + ((lane>>3)&1)*8 + (lane&7))*272
                       + wn*128 + nb2*32 + (lane>>4)*16);
                uint32_t bf0[2] = {r0, r1}, bf1[2] = {r2, r3};
                mma16(acc[0][2*nb2],   af[0], bf0);
                mma16(acc[0][2*nb2+1], af[0], bf1);
                mma16(acc[1][2*nb2],   af[1], bf0);
                mma16(acc[1][2*nb2+1], af[1], bf1);
            }
        }
    }

    // epilogue
    #pragma unroll
    for (int mt = 0; mt < 2; mt++) {
        const int rbase = row0 + wm*32 + mt*16 + lr;
        #pragma unroll
        for (int nt = 0; nt < 8; nt++) {
            const int cc = col0 + wn*64 + nt*8 + 2*lc;
            const float b0 = bias[cc], b1 = bias[cc+1];
            #pragma unroll
            for (int h2 = 0; h2 < 2; h2++) {
                const int r = rbase + h2*8;
                float v0 = acc[mt][nt][h2*2]   + b0;
                float v1 = acc[mt][nt][h2*2+1] + b1;
                if (QKV) {
                    const int part = cc >> 9;
                    const int hh   = (cc >> 6) & 7;
                    const int dd   = cc & 63;
                    const int bb   = r >> 10;
                    const int nn   = r & 1023;
                    const int bhh  = bb*NH + hh;
                    if (part == 0) { v0 *= qscale; v1 *= qscale; }
                    __half* dst = (part == 0) ? Qo : (part == 1) ? Ko : Vo;
                    *(uint32_t*)&dst[(bhh*NSEQ + nn)*DH + dd] = pkh2(v0, v1);
                } else {
                    *(float2*)&C[r*Ncols + cc] = make_float2(v0, v1);
                }
            }
        }
    }
}

// ---------------- flash attention (fp16 mma, triple-buffered) ----------------
// Block: 128 queries, 8 warps (16 rows each), 64-key tiles, single barrier/tile.
// STAGE1: mask pre-scaled by -log2e; sigmoid = RCP(1 + ex2a(s*m')) -> 4 ops/elem.
// STAGE2: log2-domain scores (qscale = SCALE*log2e); p = ex2a(s - m).
//         Deferred rescale at +11.5; lrow per-thread partial, reduced at end.
template<bool STAGE1>
__global__ __launch_bounds__(256) void attn_h(
    const __half* __restrict__ Q, const __half* __restrict__ K,
    const __half* __restrict__ V, const float* __restrict__ mask,
    __half* __restrict__ out)
{
    extern __shared__ char smc[];
    const int tid = threadIdx.x, warp = tid >> 5, lane = tid & 31;
    const int lr = lane >> 2, lc = lane & 3;
    const int bh = blockIdx.x, qt = blockIdx.y;
    const int b = bh >> 3, h = bh & 7;
    const uint32_t smb = (uint32_t)__cvta_generic_to_shared(smc);

    const __half* Qsrc = Q + (bh*NSEQ + qt*128)*DH;
    const __half* Ksrc = K + bh*NSEQ*DH;
    const __half* Vsrc = V + bh*NSEQ*DH;

    // ---- stage Q into buf 2 region, extract A-frags ----
    #pragma unroll
    for (int p = 0; p < 4; p++) {
        const int s = tid + 256*p;
        const int row = s >> 3, c8 = s & 7;
        cpa16(smb + 2*18432 + row*144 + c8*16, Qsrc + row*64 + c8*8);
    }
    CP_COMMIT();
    CP_WAIT(0);
    __syncthreads();

    uint32_t qf[4][4];
    #pragma unroll
    for (int kg = 0; kg < 4; kg++)
        ldsm4(qf[kg][0], qf[kg][1], qf[kg][2], qf[kg][3],
              smb + 2*18432 + (warp*16 + (lane & 15))*144 + (lane>>4)*16 + kg*32);
    __syncthreads();   // buf 2 free for tile 2

    // ---- prologue: tiles 0,1 -> bufs 0,1 ----
    #pragma unroll
    for (int c = 0; c < 2; c++) {
        #pragma unroll
        for (int p = 0; p < 2; p++) {
            const int s = tid + 256*p;
            const int row = s >> 3, c8 = s & 7;
            cpa16(smb + c*18432 + row*144 + c8*16,        Ksrc + (c*64 + row)*64 + c8*8);
            cpa16(smb + c*18432 + 9216 + row*144 + c8*16, Vsrc + (c*64 + row)*64 + c8*8);
        }
        CP_COMMIT();
    }

    float o[8][4] = {};
    float mrow[2] = {-1e30f, -1e30f}, lrow[2] = {0.f, 0.f};

    for (int t = 0; t < 16; t++) {
        const int bu = t % 3;
        if (t < 15) { CP_WAIT(1); } else { CP_WAIT(0); }
        __syncthreads();   // tile t ready; all warps done with tile t-1

        if (t + 2 < 16) {
            const int nb = (t+2) % 3;
            #pragma unroll
            for (int p = 0; p < 2; p++) {
                const int s = tid + 256*p;
                const int row = s >> 3, c8 = s & 7;
                cpa16(smb + nb*18432 + row*144 + c8*16,
                      Ksrc + ((t+2)*64 + row)*64 + c8*8);
                cpa16(smb + nb*18432 + 9216 + row*144 + c8*16,
                      Vsrc + ((t+2)*64 + row)*64 + c8*8);
            }
            CP_COMMIT();
        }

        const uint32_t kbuf = smb + bu*18432;

        // ---- S = Q @ K^T ----
        float s[8][4];
        #pragma unroll
        for (int nt = 0; nt < 8; nt++)
            #pragma unroll
            for (int u = 0; u < 4; u++) s[nt][u] = 0.f;
        #pragma unroll
        for (int kg = 0; kg < 4; kg++) {
            #pragma unroll
            for (int nt2 = 0; nt2 < 4; nt2++) {
                uint32_t r0, r1, r2, r3;
                ldsm4(r0, r1, r2, r3,
                      kbuf + (nt2*16 + ((lane>>4)&1)*8 + (lane&7))*144
                      + kg*32 + ((lane>>3)&1)*16);
                uint32_t bf0[2] = {r0, r1}, bf1[2] = {r2, r3};
                mma16(s[2*nt2],   qf[kg], bf0);
                mma16(s[2*nt2+1], qf[kg], bf1);
            }
        }

        // ---- elementwise ----
        if (STAGE1) {
            // mask pre-scaled by -log2e: sigmoid(z) = 1/(1 + 2^(z*m'))
            const int qrow0 = qt*128 + warp*16 + lr;
            #pragma unroll
            for (int nt = 0; nt < 8; nt++) {
                const int ccol = t*64 + nt*8 + 2*lc;
                float2 m0v = *(const float2*)(mask + qrow0*NSEQ + ccol);
                float2 m1v = *(const float2*)(mask + (qrow0+8)*NSEQ + ccol);
                s[nt][0] = __fdividef(1.f, 1.f + ex2a(s[nt][0]*m0v.x));
                s[nt][1] = __fdividef(1.f, 1.f + ex2a(s[nt][1]*m0v.y));
                s[nt][2] = __fdividef(1.f, 1.f + ex2a(s[nt][2]*m1v.x));
                s[nt][3] = __fdividef(1.f, 1.f + ex2a(s[nt][3]*m1v.y));
            }
        } else {
            // per-row tile max (trigger only); log2 domain
            float tmax[2];
            #pragma unroll
            for (int h2 = 0; h2 < 2; h2++) {
                float tm = -1e30f;
                #pragma unroll
                for (int nt = 0; nt < 8; nt++)
                    tm = fmaxf(tm, fmaxf(s[nt][h2*2], s[nt][h2*2+1]));
                tm = fmaxf(tm, __shfl_xor_sync(0xffffffffu, tm, 1));
                tm = fmaxf(tm, __shfl_xor_sync(0xffffffffu, tm, 2));
                tmax[h2] = tm;
            }
            // deferred rescale: p <= 2^11.5 stays inside fp16 range
            const bool trig = (tmax[0] > mrow[0] + 11.5f) || (tmax[1] > mrow[1] + 11.5f);
            if (__any_sync(0xffffffffu, trig)) {
                #pragma unroll
                for (int h2 = 0; h2 < 2; h2++) {
                    const float mnew  = fmaxf(mrow[h2], tmax[h2]);
                    const float alpha = ex2a(mrow[h2] - mnew);
                    lrow[h2] *= alpha;
                    #pragma unroll
                    for (int nt = 0; nt < 8; nt++) {
                        o[nt][h2*2]   *= alpha;
                        o[nt][h2*2+1] *= alpha;
                    }
                    mrow[h2] = mnew;
                }
            }
            #pragma unroll
            for (int h2 = 0; h2 < 2; h2++) {
                float rs = 0.f;
                #pragma unroll
                for (int nt = 0; nt < 8; nt++) {
                    const float p0 = ex2a(s[nt][h2*2]   - mrow[h2]);
                    const float p1 = ex2a(s[nt][h2*2+1] - mrow[h2]);
                    rs += p0 + p1;
                    s[nt][h2*2]   = p0;
                    s[nt][h2*2+1] = p1;
                }
                lrow[h2] += rs;   // per-thread partial; quad-reduced at the end
            }
        }

        // ---- C-frag -> fp16 A-frag: pure register packing ----
        uint32_t pa[4][4];
        #pragma unroll
        for (int kt2 = 0; kt2 < 4; kt2++) {
            pa[kt2][0] = pkh2(s[2*kt2][0],   s[2*kt2][1]);
            pa[kt2][1] = pkh2(s[2*kt2][2],   s[2*kt2][3]);
            pa[kt2][2] = pkh2(s[2*kt2+1][0], s[2*kt2+1][1]);
            pa[kt2][3] = pkh2(s[2*kt2+1][2], s[2*kt2+1][3]);
        }

        // ---- O += P @ V : trans ldsm on row-major V ----
        const uint32_t vbuf = kbuf + 9216;
        #pragma unroll
        for (int kg = 0; kg < 4; kg++) {
            #pragma unroll
            for (int nb2 = 0; nb2 < 4; nb2++) {
                uint32_t r0, r1, r2, r3;
                ldsm4t(r0, r1, r2, r3,
                       vbuf + (kg*16 + ((lane>>3)&1)*8 + (lane&7))*144
                       + nb2*32 + (lane>>4)*16);
                uint32_t bf0[2] = {r0, r1}, bf1[2] = {r2, r3};
                mma16(o[2*nb2],   pa[kg], bf0);
                mma16(o[2*nb2+1], pa[kg], bf1);
            }
        }
    }

    // ---- final lrow reduction across the lane quad (stage 2 only) ----
    if (!STAGE1) {
        #pragma unroll
        for (int h2 = 0; h2 < 2; h2++) {
            float l = lrow[h2];
            l += __shfl_xor_sync(0xffffffffu, l, 1);
            l += __shfl_xor_sync(0xffffffffu, l, 2);
            lrow[h2] = l;
        }
    }

    // ---- epilogue: half output (feeds next GEMM) ----
    __half* obase = out + b*NSEQ*DIM + h*DH;
    #pragma unroll
    for (int h2 = 0; h2 < 2; h2++) {
        const float inv = STAGE1 ? 1.f : __fdividef(1.f, lrow[h2]);
        const int n = qt*128 + warp*16 + lr + h2*8;
        #pragma unroll
        for (int nt = 0; nt < 8; nt++)
            *(uint32_t*)&obase[n*DIM + nt*8 + 2*lc] =
                pkh2(o[nt][h2*2]*inv, o[nt][h2*2+1]*inv);
    }
}

// ---------------- launch ----------------
extern "C" void kernel_launch(void* const* d_in, const int* in_sizes, int n_in,
                              void* d_out, int out_size)
{
    const float* x     = (const float*)d_in[0];
    const float* mask  = (const float*)d_in[1];
    const float* Wqkv1 = (const float*)d_in[2];
    const float* bqkv1 = (const float*)d_in[3];
    const float* Wqkv2 = (const float*)d_in[4];
    const float* bqkv2 = (const float*)d_in[5];
    const float* Wnn1  = (const float*)d_in[6];
    const float* bnn1  = (const float*)d_in[7];
    float* out = (float*)d_out;

    __half *q1, *k1, *v1, *o1, *q2, *k2, *v2, *att, *xh, *w1, *w2, *wn;
    float* mask2;
    cudaGetSymbolAddress((void**)&q1, g_q1);
    cudaGetSymbolAddress((void**)&k1, g_k1);
    cudaGetSymbolAddress((void**)&v1, g_v1);
    cudaGetSymbolAddress((void**)&o1, g_o1);
    cudaGetSymbolAddress((void**)&q2, g_q2);
    cudaGetSymbolAddress((void**)&k2, g_k2);
    cudaGetSymbolAddress((void**)&v2, g_v2);
    cudaGetSymbolAddress((void**)&att, g_att);
    cudaGetSymbolAddress((void**)&xh, g_xh);
    cudaGetSymbolAddress((void**)&w1, g_w1);
    cudaGetSymbolAddress((void**)&w2, g_w2);
    cudaGetSymbolAddress((void**)&wn, g_wn);
    cudaGetSymbolAddress((void**)&mask2, g_mask2);

    const int GSMEM = 56832, ASMEM = 55296;
    cudaFuncSetAttribute(gemm_h<1>, cudaFuncAttributeMaxDynamicSharedMemorySize, GSMEM);
    cudaFuncSetAttribute(gemm_h<0>, cudaFuncAttributeMaxDynamicSharedMemorySize, GSMEM);
    cudaFuncSetAttribute(attn_h<true>,  cudaFuncAttributeMaxDynamicSharedMemorySize, ASMEM);
    cudaFuncSetAttribute(attn_h<false>, cudaFuncAttributeMaxDynamicSharedMemorySize, ASMEM);

    const int M = BATCH * NSEQ;   // 8192
    const int n0 = M*DIM/8, n1 = DIM*3*DIM/8, n2 = n1, n3 = DIM*DIM/8;
    const int n4 = NSEQ*NSEQ/4;

    cvt_all<<<(n0+n1+n2+n3+n4 + 255)/256, 256>>>(
        (const float4*)x, (uint4*)xh, n0,
        (const float4*)Wqkv1, (uint4*)w1, n1,
        (const float4*)Wqkv2, (uint4*)w2, n2,
        (const float4*)Wnn1, (uint4*)wn, n3,
        (const float4*)mask, (float4*)mask2, n4);

    dim3 gridQKV(3*DIM/128, M/128);   // 12 x 64
    dim3 gridOut(DIM/128, M/128);     // 4 x 64
    dim3 gridAtt(BH, NSEQ/128);       // 64 x 8

    // Stage 1: plain Q; sigmoid via pre-scaled mask (-log2e folded)
    gemm_h<1><<<gridQKV, 256, GSMEM>>>(xh, w1, bqkv1, nullptr, q1, k1, v1, 3*DIM, 1.f);
    attn_h<true><<<gridAtt, 256, ASMEM>>>(q1, k1, v1, mask2, o1);
    // Stage 2: Q scaled by SCALE*log2e (log2-domain softmax)
    gemm_h<1><<<gridQKV, 256, GSMEM>>>(o1, w2, bqkv2, nullptr, q2, k2, v2, 3*DIM, SCALE*LOG2E);
    attn_h<false><<<gridAtt, 256, ASMEM>>>(q2, k2, v2, nullptr, att);
    gemm_h<0><<<gridOut, 256, GSMEM>>>(att, wn, bnn1, out, nullptr, nullptr, nullptr, DIM, 1.f);
}